// round 2
// baseline (speedup 1.0000x reference)
#include <cuda_runtime.h>
#include <math.h>

// Problem constants
#define B_  16
#define N_  577
#define D_  1024
#define E_  8
#define R_  16
#define C3_ 3072
#define TOPK 2

// Output layout (all six reference outputs concatenated, fp32)
#define WU_SIZE   (B_ * N_ * C3_)          // 28,366,848
#define RL_OFF    (WU_SIZE)                // router_logits [16,8]
#define TI_OFF    (RL_OFF + B_ * E_)       // top_idx as float [16,2]
#define EW_OFF    (TI_OFF + B_ * TOPK)     // expert_weights [16,8]
#define IMP_OFF   (EW_OFF + B_ * E_)       // importance [8]
#define LOAD_OFF  (IMP_OFF + E_)           // load [8]
#define OUT_TOTAL (LOAD_OFF + E_)          // 28,367,152

// Scratch (no allocations allowed -> device globals)
__device__ float g_pooled[B_ * D_];   // token sums over N
__device__ float g_logits[B_ * E_];
__device__ int   g_sel[B_ * TOPK];
__device__ float g_coef[B_ * TOPK];   // softmax weight * scaling, folded into U

// ---------------------------------------------------------------------------
// Kernel 0: zero pooled scratch (must rerun every graph replay)
// ---------------------------------------------------------------------------
__global__ void zero_pooled_kernel() {
    g_pooled[blockIdx.x * 1024 + threadIdx.x] = 0.0f;
}

// ---------------------------------------------------------------------------
// Kernel 1: pooled[b][d] = sum_n tokens[b][n][d]  (partial sums + atomics)
// grid (8 chunks, 16 batches), 256 threads; thread owns 4 consecutive d (float4)
// ---------------------------------------------------------------------------
__global__ void pool_kernel(const float* __restrict__ tokens) {
    int b = blockIdx.y;
    int chunk = blockIdx.x;
    int t = threadIdx.x;
    int n0 = chunk * 73;
    int n1 = min(N_, n0 + 73);

    float4 acc = make_float4(0.f, 0.f, 0.f, 0.f);
    const float* base = tokens + ((size_t)b * N_) * D_;
    for (int n = n0; n < n1; n++) {
        float4 v = *(const float4*)&base[n * D_ + t * 4];
        acc.x += v.x; acc.y += v.y; acc.z += v.z; acc.w += v.w;
    }
    float* p = &g_pooled[b * D_ + t * 4];
    atomicAdd(p + 0, acc.x);
    atomicAdd(p + 1, acc.y);
    atomicAdd(p + 2, acc.z);
    atomicAdd(p + 3, acc.w);
}

// ---------------------------------------------------------------------------
// Kernel 2: router logits. One warp per (b, e). 4 blocks x 1024 threads.
// logits[b][e] = (1/N) * sum_d pooled_sum[b][d] * gate_w[d][e]
// ---------------------------------------------------------------------------
__global__ void router_kernel(const float* __restrict__ gate_w,
                              float* __restrict__ out, int write_aux) {
    int w = blockIdx.x * (blockDim.x / 32) + threadIdx.x / 32;
    int lane = threadIdx.x & 31;
    if (w >= B_ * E_) return;
    int b = w / E_;
    int e = w % E_;

    float acc = 0.f;
    for (int d = lane; d < D_; d += 32)
        acc += g_pooled[b * D_ + d] * gate_w[d * E_ + e];
    #pragma unroll
    for (int off = 16; off > 0; off >>= 1)
        acc += __shfl_down_sync(0xffffffffu, acc, off);
    if (lane == 0) {
        float lg = acc * (1.0f / (float)N_);
        g_logits[b * E_ + e] = lg;
        if (write_aux) out[RL_OFF + b * E_ + e] = lg;
    }
}

// ---------------------------------------------------------------------------
// Kernel 3: top-2 + softmax + small outputs + per-batch selection scratch
// single block, 128 threads
// ---------------------------------------------------------------------------
__global__ void topk_kernel(const float* __restrict__ scaling,
                            float* __restrict__ out, int write_aux) {
    __shared__ float ew[B_][E_];
    __shared__ int   sel_s[B_][TOPK];
    int t = threadIdx.x;

    if (t < B_ * E_) ew[t / E_][t % E_] = 0.0f;
    __syncthreads();

    if (t < B_) {
        int b = t;
        float v[E_];
        #pragma unroll
        for (int e = 0; e < E_; e++) v[e] = g_logits[b * E_ + e];
        int m1 = 0;
        #pragma unroll
        for (int e = 1; e < E_; e++) if (v[e] > v[m1]) m1 = e;
        int m2 = (m1 == 0) ? 1 : 0;
        #pragma unroll
        for (int e = 0; e < E_; e++)
            if (e != m1 && v[e] > v[m2]) m2 = e;

        float e2 = expf(v[m2] - v[m1]);
        float inv = 1.0f / (1.0f + e2);
        float w1 = inv;
        float w2 = e2 * inv;

        ew[b][m1] = w1;
        ew[b][m2] = w2;
        sel_s[b][0] = m1;
        sel_s[b][1] = m2;
        g_sel[b * 2 + 0] = m1;
        g_sel[b * 2 + 1] = m2;
        g_coef[b * 2 + 0] = w1 * scaling[m1];
        g_coef[b * 2 + 1] = w2 * scaling[m2];
        if (write_aux) {
            out[TI_OFF + b * 2 + 0] = (float)m1;
            out[TI_OFF + b * 2 + 1] = (float)m2;
        }
    }
    __syncthreads();

    if (write_aux) {
        if (t < B_ * E_) out[EW_OFF + t] = ew[t / E_][t % E_];
        if (t < E_) {
            float imp = 0.f;
            int ld = 0;
            for (int b = 0; b < B_; b++) {
                imp += ew[b][t];
                ld += (sel_s[b][0] == t) + (sel_s[b][1] == t);
            }
            out[IMP_OFF + t] = imp;
            out[LOAD_OFF + t] = (float)ld;
        }
    }
}

// ---------------------------------------------------------------------------
// Kernel 4: fused per-(batch, 32-token tile):
//   Phase 1: U[32n x 32j] = T[32 x 1024] @ Asel^T ; fold coef into U
//   Phase 2: out[32n x 3072c] = U @ Bsel^T, streamed in 128-wide C chunks
// ---------------------------------------------------------------------------
#define NT 32     // token rows per block
#define KC 64     // k-chunk in phase 1
#define CC 128    // c-chunk in phase 2

__global__ __launch_bounds__(256)
void moe_lora_kernel(const float* __restrict__ tokens,
                     const float* __restrict__ lora_a,
                     const float* __restrict__ lora_b,
                     float* __restrict__ out) {
    __shared__ union {
        struct { float T[NT][KC + 4]; float A[NT][KC + 4]; } p1;  // 17,408 B
        float Bm[CC][36];                                         // 18,432 B
    } sm;
    __shared__ float Usm[NT][36];

    const int b  = blockIdx.y;
    const int n0 = blockIdx.x * NT;
    const int tid = threadIdx.x;
    const int ty = tid / 32;      // 0..7
    const int tx = tid & 31;      // 0..31

    const int s0 = g_sel[b * 2 + 0];
    const int s1 = g_sel[b * 2 + 1];
    const float c0f = g_coef[b * 2 + 0];
    const float c1f = g_coef[b * 2 + 1];

    // ---------------- Phase 1: U tile ----------------
    // thread computes U[4*ty + i][tx], i = 0..3
    float acc[4] = {0.f, 0.f, 0.f, 0.f};
    const int tok_base = (b * N_ + n0) * D_;

    for (int k0 = 0; k0 < D_; k0 += KC) {
        // load T (32 x 64) and A (32 x 64) as float4s: 512 vec4 each, 2/thread
        #pragma unroll
        for (int i = 0; i < 2; i++) {
            int idx = tid + i * 256;
            int r = idx >> 4;          // 0..31
            int q = idx & 15;          // 0..15
            float4 tv = make_float4(0.f, 0.f, 0.f, 0.f);
            if (n0 + r < N_)
                tv = *(const float4*)&tokens[tok_base + r * D_ + k0 + q * 4];
            *(float4*)&sm.p1.T[r][q * 4] = tv;

            int e  = (r < 16) ? s0 : s1;
            const float* ar = lora_a + ((e * R_ + (r & 15)) * D_);
            *(float4*)&sm.p1.A[r][q * 4] = *(const float4*)&ar[k0 + q * 4];
        }
        __syncthreads();

        #pragma unroll
        for (int kk = 0; kk < KC; kk += 4) {
            float4 av = *(const float4*)&sm.p1.A[tx][kk];
            #pragma unroll
            for (int i = 0; i < 4; i++) {
                float4 tv = *(const float4*)&sm.p1.T[ty * 4 + i][kk];
                acc[i] += tv.x * av.x + tv.y * av.y + tv.z * av.z + tv.w * av.w;
            }
        }
        __syncthreads();
    }

    // fold gating coefficient (w * scaling) into U
    {
        float cf = (tx < 16) ? c0f : c1f;
        #pragma unroll
        for (int i = 0; i < 4; i++)
            Usm[ty * 4 + i][tx] = acc[i] * cf;
    }
    __syncthreads();

    // ---------------- Phase 2: output tile ----------------
    // thread computes out rows n = ty + 8*i (i<4), cols c = c0 + tx + 32*l (l<4)
    const int out_base = (b * N_ + n0) * C3_;

    for (int c0 = 0; c0 < C3_; c0 += CC) {
        // load combined B chunk: row c holds [lora_b[s0][c][:16], lora_b[s1][c][:16]]
        #pragma unroll
        for (int i = 0; i < 4; i++) {
            int idx = tid + i * 256;
            int c = idx >> 3;          // 0..127
            int q = idx & 7;           // 0..7 (vec4 within 32-wide row)
            int e = (q < 4) ? s0 : s1;
            const float4* src =
                (const float4*)&lora_b[(e * C3_ + c0 + c) * R_ + (q & 3) * 4];
            *(float4*)&sm.Bm[c][q * 4] = *src;
        }
        __syncthreads();

        float o[4][4];
        #pragma unroll
        for (int i = 0; i < 4; i++)
            #pragma unroll
            for (int l = 0; l < 4; l++) o[i][l] = 0.f;

        #pragma unroll
        for (int j4 = 0; j4 < 32; j4 += 4) {
            float4 u0 = *(const float4*)&Usm[ty +  0][j4];
            float4 u1 = *(const float4*)&Usm[ty +  8][j4];
            float4 u2 = *(const float4*)&Usm[ty + 16][j4];
            float4 u3 = *(const float4*)&Usm[ty + 24][j4];
            #pragma unroll
            for (int l = 0; l < 4; l++) {
                float4 bv = *(const float4*)&sm.Bm[tx + 32 * l][j4];
                o[0][l] += u0.x * bv.x + u0.y * bv.y + u0.z * bv.z + u0.w * bv.w;
                o[1][l] += u1.x * bv.x + u1.y * bv.y + u1.z * bv.z + u1.w * bv.w;
                o[2][l] += u2.x * bv.x + u2.y * bv.y + u2.z * bv.z + u2.w * bv.w;
                o[3][l] += u3.x * bv.x + u3.y * bv.y + u3.z * bv.z + u3.w * bv.w;
            }
        }

        #pragma unroll
        for (int i = 0; i < 4; i++) {
            int n = ty + 8 * i;
            if (n0 + n < N_) {
                float* orow = &out[out_base + n * C3_ + c0 + tx];
                orow[0]  = o[i][0];
                orow[32] = o[i][1];
                orow[64] = o[i][2];
                orow[96] = o[i][3];
            }
        }
        __syncthreads();
    }
}

// ---------------------------------------------------------------------------
extern "C" void kernel_launch(void* const* d_in, const int* in_sizes, int n_in,
                              void* d_out, int out_size) {
    const float* tokens  = (const float*)d_in[0];
    const float* gate_w  = (const float*)d_in[1];
    const float* lora_a  = (const float*)d_in[2];
    const float* lora_b  = (const float*)d_in[3];
    const float* scaling = (const float*)d_in[4];
    float* out = (float*)d_out;

    int write_aux = (out_size >= OUT_TOTAL) ? 1 : 0;

    zero_pooled_kernel<<<B_, 1024>>>();
    pool_kernel<<<dim3(8, B_), 256>>>(tokens);
    router_kernel<<<4, 1024>>>(gate_w, out, write_aux);
    topk_kernel<<<1, 128>>>(scaling, out, write_aux);
    moe_lora_kernel<<<dim3((N_ + NT - 1) / NT, B_), 256>>>(tokens, lora_a, lora_b, out);
}